// round 14
// baseline (speedup 1.0000x reference)
#include <cuda_runtime.h>
#include <cuda_bf16.h>
#include <cuda_fp16.h>
#include <cstdint>

#define NN 100000
#define NE 1600000
#define DD 128
#define NB_TILES 1563          // ceil(NN/64)
#define GRID_P 296             // 2 CTAs/SM x 148 SMs

// ======================= helpers ============================================
__device__ __forceinline__ uint32_t smem_to_u32(const void* p) {
    uint32_t a;
    asm("{ .reg .u64 t; cvta.to.shared.u64 t, %1; cvt.u32.u64 %0, t; }" : "=r"(a) : "l"(p));
    return a;
}
__device__ __forceinline__ void ldsm_x4(uint32_t& r0, uint32_t& r1, uint32_t& r2, uint32_t& r3,
                                        uint32_t addr) {
    asm volatile("ldmatrix.sync.aligned.m8n8.x4.shared.b16 {%0,%1,%2,%3}, [%4];"
                 : "=r"(r0), "=r"(r1), "=r"(r2), "=r"(r3) : "r"(addr));
}
__device__ __forceinline__ void mma16816(float* c, uint32_t a0, uint32_t a1, uint32_t a2,
                                         uint32_t a3, uint32_t b0, uint32_t b1) {
    asm volatile("mma.sync.aligned.m16n8k16.row.col.f32.bf16.bf16.f32 "
                 "{%0,%1,%2,%3}, {%4,%5,%6,%7}, {%8,%9}, {%0,%1,%2,%3};"
                 : "+f"(c[0]), "+f"(c[1]), "+f"(c[2]), "+f"(c[3])
                 : "r"(a0), "r"(a1), "r"(a2), "r"(a3), "r"(b0), "r"(b1));
}
// swizzled byte offset of bf16 element (r, c) in a row=256B tile
__device__ __host__ __forceinline__ uint32_t sw_off(int r, int c) {
    int c2 = c >> 3;
    int sw = (c2 & 8) | ((c2 ^ r) & 7);
    return (uint32_t)(r * 256 + (sw << 4) + (c & 7) * 2);
}

// ======================= scratch (device globals) ===========================
__device__ __align__(16) __nv_bfloat16 g_Ahi[(size_t)NN * DD];  // h0 hi image
__device__ __align__(16) __nv_bfloat16 g_Alo[(size_t)NN * DD];  // h0 lo image
__device__ __align__(16) __half g_msgA[(size_t)NN * DD];  // msg ping
__device__ __align__(16) __half g_msgB[(size_t)NN * DD];  // msg pong
__device__ float  g_colsum[DD];
__device__ float  g_colsq[DD];
__device__ float  g_bnscale[DD];
__device__ float  g_bnshift[DD];
__device__ int    g_outdeg[NN];
__device__ int    g_indeg[NN];
__device__ float  g_nsrc[NN];
__device__ float  g_ndst[NN];
__device__ int    g_rowptr[NN + 1];
__device__ int    g_cursor[NN];
__device__ int    g_csrsrc[NE];
__device__ int    g_bsums[128];
__device__ __align__(16) __nv_bfloat16 g_Whi[3][16384];
__device__ __align__(16) __nv_bfloat16 g_Wlo[3][16384];

// ======================= graph-side kernels =================================
__global__ void init_graph_k() {
    int i = blockIdx.x * blockDim.x + threadIdx.x;
    if (i < NN) { g_outdeg[i] = 0; g_indeg[i] = 0; }
}

__global__ void degree_k(const int* __restrict__ src, const int* __restrict__ dst) {
    int i = blockIdx.x * blockDim.x + threadIdx.x;
    if (i < NE) {
        atomicAdd(&g_outdeg[src[i]], 1);
        atomicAdd(&g_indeg[dst[i]], 1);
    }
}

__global__ void scanA_k() {
    __shared__ int sdata[1024];
    int t = threadIdx.x;
    int i = blockIdx.x * 1024 + t;
    int x = (i < NN) ? g_indeg[i] : 0;
    if (i < NN) {
        g_nsrc[i] = rsqrtf((float)max(g_outdeg[i], 1));
        g_ndst[i] = rsqrtf((float)max(x, 1));
    }
    sdata[t] = x;
    __syncthreads();
    for (int off = 1; off < 1024; off <<= 1) {
        int v = (t >= off) ? sdata[t - off] : 0;
        __syncthreads();
        sdata[t] += v;
        __syncthreads();
    }
    if (i < NN) g_rowptr[i] = sdata[t] - x;
    if (t == 1023) g_bsums[blockIdx.x] = sdata[1023];
}

__global__ void scanB_k(int nblocks) {
    __shared__ int s[128];
    int t = threadIdx.x;
    int v = (t < nblocks) ? g_bsums[t] : 0;
    s[t] = v;
    __syncthreads();
    for (int off = 1; off < 128; off <<= 1) {
        int u = (t >= off) ? s[t - off] : 0;
        __syncthreads();
        s[t] += u;
        __syncthreads();
    }
    if (t < nblocks) g_bsums[t] = s[t] - v;
}

__global__ void scanC_k() {
    int i = blockIdx.x * blockDim.x + threadIdx.x;
    if (i < NN) {
        int v = g_rowptr[i] + g_bsums[i >> 10];
        g_rowptr[i] = v;
        g_cursor[i] = v;
    }
    if (i == 0) g_rowptr[NN] = NE;
}

__global__ void csrfill_k(const int* __restrict__ src, const int* __restrict__ dst) {
    int i = blockIdx.x * blockDim.x + threadIdx.x;
    if (i < NE) {
        int pos = atomicAdd(&g_cursor[dst[i]], 1);
        g_csrsrc[pos] = src[i];
    }
}

// ======================= MLP-side small kernels =============================
__global__ void prep_w_all(const float* __restrict__ W1, const float* __restrict__ W2,
                           const float* __restrict__ Wc) {
    if (blockIdx.x == 0 && threadIdx.x < DD) {
        g_colsum[threadIdx.x] = 0.f;
        g_colsq[threadIdx.x] = 0.f;
    }
    int slot = blockIdx.x >> 6;
    const float* W = (slot == 0) ? W1 : (slot == 1) ? W2 : Wc;
    int idx = (blockIdx.x & 63) * 256 + threadIdx.x;
    int n = idx >> 7, k = idx & 127;
    float w = W[k * DD + n];
    __nv_bfloat16 hi = __float2bfloat16(w);
    float r = w - __bfloat162float(hi);
    __nv_bfloat16 lo = __float2bfloat16(r);
    uint32_t o = sw_off(n, k) >> 1;
    g_Whi[slot][o] = hi;
    g_Wlo[slot][o] = lo;
}

__global__ void bn_finalize_k(const float* __restrict__ gamma, const float* __restrict__ beta) {
    int c = threadIdx.x;
    if (c < DD) {
        float inv_n = 1.f / (float)NN;
        float mean = g_colsum[c] * inv_n;
        float var = g_colsq[c] * inv_n - mean * mean;
        float rs = rsqrtf(var + 1e-5f);
        float gsc = gamma[c] * rs;
        g_bnscale[c] = gsc;
        g_bnshift[c] = beta[c] - mean * gsc;
    }
}

// ======================= persistent tensor-core GEMM ========================
// Grid-stride over 64-row tiles; B images loaded ONCE per CTA.
// ALOAD: 0 cvt from fp32 ext, 1 bn+relu from split h0 images, 3 fused gather.
// EPI:   0 v=acc+bias, 1 v=acc*ndst+bias.
// OUT:   0 fp32 -> Cext, 1 fp16 msg = relu(v)*nsrc, 2 split bf16 images.
// STATS: accumulate column sum/sumsq of v (register-resident across tiles).
// MSGSEL: gather READS (0 ? msgA : msgB); msg epilogue WRITES the other one.
#define SM_BIAS  0
#define SM_AHI   1024
#define SM_ALO   17408
#define SM_BHI   33792
#define SM_BLO   66560
#define SM_STATS 99328
#define SM_TOTAL 103424

template <int ALOAD, int EPI, int OUT, int STATS, int MSGSEL>
__global__ void __launch_bounds__(256, 2)
gemm_mma(const float* __restrict__ Aext,
         int wslot,
         const float* __restrict__ bias,
         float* __restrict__ Cext)
{
    extern __shared__ char smem[];
    uint32_t sb = smem_to_u32(smem);
    int tid = threadIdx.x;
    int lane = tid & 31;
    int wid = tid >> 5;
    int wm = wid >> 1;          // 0..3 : M split (16 rows each)
    int wn = wid & 1;           // 0..1 : N split (64 cols each)

    const __half* msgRd = (MSGSEL == 0) ? g_msgA : g_msgB;   // gather source
    __half*       msgWr = (MSGSEL == 0) ? g_msgB : g_msgA;   // epilogue dest

    if (tid < 32) ((float4*)(smem + SM_BIAS))[tid] = ((const float4*)bias)[tid];

    // B images: load ONCE (2 x 32 KB, pre-swizzled layout)
    {
        const uint4* bh = (const uint4*)g_Whi[wslot];
        const uint4* bl = (const uint4*)g_Wlo[wslot];
        uint4* sh = (uint4*)(smem + SM_BHI);
        uint4* sl = (uint4*)(smem + SM_BLO);
#pragma unroll
        for (int i = 0; i < 8; i++) {
            sh[tid + i * 256] = bh[tid + i * 256];
            sl[tid + i * 256] = bl[tid + i * 256];
        }
    }

    // register-resident stats accumulators (valid on lanes 0-3)
    float sst[STATS ? 8 : 1][4];
    if (STATS)
#pragma unroll
        for (int nb = 0; nb < 8; nb++)
#pragma unroll
            for (int j = 0; j < 4; j++) sst[nb][j] = 0.f;

    const int ar = wm * 16 + (lane & 15);
    const int akh = lane >> 4;
    const int bn = lane & 7;
    const int bkh = (lane >> 3) & 1;
    const uint32_t bRegion = sb + ((lane >> 4) ? SM_BLO : SM_BHI);
    const float* sbias = (const float*)(smem + SM_BIAS);

    for (int tile = blockIdx.x; tile < NB_TILES; tile += GRID_P) {
        int rowBase = tile * 64;
        __syncthreads();   // prev mainloop done with smem A (and B copy on iter 0)

        // ---- A tile fill (64 rows) ------------------------------------------
        if (ALOAD == 0) {
            // fp32 external -> split bf16, swizzled
#pragma unroll
            for (int i = 0; i < 8; i++) {
                int t = tid + i * 256;          // 0..2047
                int r = t >> 5, q = t & 31;
                int gr = rowBase + r;
                float4 v = make_float4(0.f, 0.f, 0.f, 0.f);
                if (gr < NN) v = ((const float4*)Aext)[(size_t)gr * 32 + q];
                __nv_bfloat162 h01 = __floats2bfloat162_rn(v.x, v.y);
                __nv_bfloat162 h23 = __floats2bfloat162_rn(v.z, v.w);
                float lx = v.x - __bfloat162float(__low2bfloat16(h01));
                float ly = v.y - __bfloat162float(__high2bfloat16(h01));
                float lz = v.z - __bfloat162float(__low2bfloat16(h23));
                float lw = v.w - __bfloat162float(__high2bfloat16(h23));
                __nv_bfloat162 l01 = __floats2bfloat162_rn(lx, ly);
                __nv_bfloat162 l23 = __floats2bfloat162_rn(lz, lw);
                uint32_t off = sw_off(r, q * 4);
                asm volatile("st.shared.v2.b32 [%0], {%1, %2};" :: "r"(sb + SM_AHI + off),
                             "r"(*(uint32_t*)&h01), "r"(*(uint32_t*)&h23) : "memory");
                asm volatile("st.shared.v2.b32 [%0], {%1, %2};" :: "r"(sb + SM_ALO + off),
                             "r"(*(uint32_t*)&l01), "r"(*(uint32_t*)&l23) : "memory");
            }
        } else if (ALOAD == 1) {
            // split h0 images -> reconstruct, BN+ReLU, re-split
#pragma unroll
            for (int i = 0; i < 8; i++) {
                int t = tid + i * 256;          // 0..2047
                int r = t >> 5, q = t & 31;     // row, uint32 col-pair (2 cols)
                int gr = rowBase + r;
                uint32_t hw = 0, lw2 = 0;
                if (gr < NN) {
                    hw = ((const uint32_t*)g_Ahi)[(size_t)gr * 64 + q * 2 + 0];
                    lw2 = ((const uint32_t*)g_Ahi)[(size_t)gr * 64 + q * 2 + 1];
                }
                uint32_t hw2 = 0, lw3 = 0;
                if (gr < NN) {
                    hw2 = ((const uint32_t*)g_Alo)[(size_t)gr * 64 + q * 2 + 0];
                    lw3 = ((const uint32_t*)g_Alo)[(size_t)gr * 64 + q * 2 + 1];
                }
                float4 sc = ((const float4*)g_bnscale)[q];
                float4 shp = ((const float4*)g_bnshift)[q];
                __nv_bfloat162 ha = *(__nv_bfloat162*)&hw;
                __nv_bfloat162 la = *(__nv_bfloat162*)&hw2;
                __nv_bfloat162 hb = *(__nv_bfloat162*)&lw2;
                __nv_bfloat162 lb = *(__nv_bfloat162*)&lw3;
                float f0 = __bfloat162float(__low2bfloat16(ha)) + __bfloat162float(__low2bfloat16(la));
                float f1 = __bfloat162float(__high2bfloat16(ha)) + __bfloat162float(__high2bfloat16(la));
                float f2 = __bfloat162float(__low2bfloat16(hb)) + __bfloat162float(__low2bfloat16(lb));
                float f3 = __bfloat162float(__high2bfloat16(hb)) + __bfloat162float(__high2bfloat16(lb));
                f0 = fmaxf(fmaf(f0, sc.x, shp.x), 0.f);
                f1 = fmaxf(fmaf(f1, sc.y, shp.y), 0.f);
                f2 = fmaxf(fmaf(f2, sc.z, shp.z), 0.f);
                f3 = fmaxf(fmaf(f3, sc.w, shp.w), 0.f);
                __nv_bfloat162 h01 = __floats2bfloat162_rn(f0, f1);
                __nv_bfloat162 h23 = __floats2bfloat162_rn(f2, f3);
                __nv_bfloat162 l01 = __floats2bfloat162_rn(
                    f0 - __bfloat162float(__low2bfloat16(h01)),
                    f1 - __bfloat162float(__high2bfloat16(h01)));
                __nv_bfloat162 l23 = __floats2bfloat162_rn(
                    f2 - __bfloat162float(__low2bfloat16(h23)),
                    f3 - __bfloat162float(__high2bfloat16(h23)));
                uint32_t off = sw_off(r, q * 4);
                asm volatile("st.shared.v2.b32 [%0], {%1, %2};" :: "r"(sb + SM_AHI + off),
                             "r"(*(uint32_t*)&h01), "r"(*(uint32_t*)&h23) : "memory");
                asm volatile("st.shared.v2.b32 [%0], {%1, %2};" :: "r"(sb + SM_ALO + off),
                             "r"(*(uint32_t*)&l01), "r"(*(uint32_t*)&l23) : "memory");
            }
        } else {
            // ALOAD==3: fused pull-gather from fp16 msgRd, 4 nodes interleaved/warp
            const uint2* m = (const uint2*)msgRd;
#pragma unroll
            for (int g = 0; g < 2; g++) {
                float4 a[4];
                int e[4], en[4];
#pragma unroll
                for (int p = 0; p < 4; p++) {
                    a[p] = make_float4(0.f, 0.f, 0.f, 0.f);
                    int node = rowBase + wid * 8 + g * 4 + p;
                    if (node < NN) { e[p] = g_rowptr[node]; en[p] = g_rowptr[node + 1]; }
                    else { e[p] = 0; en[p] = 0; }
                }
                bool more = (e[0] < en[0]) | (e[1] < en[1]) | (e[2] < en[2]) | (e[3] < en[3]);
                while (more) {
                    more = false;
#pragma unroll
                    for (int p = 0; p < 4; p++) {
                        if (e[p] < en[p]) {
                            int s = g_csrsrc[e[p]];
                            e[p]++;
                            uint2 v = m[(size_t)s * 32 + lane];
                            float2 f0 = __half22float2(*(const __half2*)&v.x);
                            float2 f1 = __half22float2(*(const __half2*)&v.y);
                            a[p].x += f0.x; a[p].y += f0.y; a[p].z += f1.x; a[p].w += f1.y;
                            if (e[p] < en[p]) more = true;
                        }
                    }
                }
#pragma unroll
                for (int p = 0; p < 4; p++) {
                    int r = wid * 8 + g * 4 + p;
                    __nv_bfloat162 h01 = __floats2bfloat162_rn(a[p].x, a[p].y);
                    __nv_bfloat162 h23 = __floats2bfloat162_rn(a[p].z, a[p].w);
                    __nv_bfloat162 l01 = __floats2bfloat162_rn(
                        a[p].x - __bfloat162float(__low2bfloat16(h01)),
                        a[p].y - __bfloat162float(__high2bfloat16(h01)));
                    __nv_bfloat162 l23 = __floats2bfloat162_rn(
                        a[p].z - __bfloat162float(__low2bfloat16(h23)),
                        a[p].w - __bfloat162float(__high2bfloat16(h23)));
                    uint32_t off = sw_off(r, lane * 4);
                    asm volatile("st.shared.v2.b32 [%0], {%1, %2};" :: "r"(sb + SM_AHI + off),
                                 "r"(*(uint32_t*)&h01), "r"(*(uint32_t*)&h23) : "memory");
                    asm volatile("st.shared.v2.b32 [%0], {%1, %2};" :: "r"(sb + SM_ALO + off),
                                 "r"(*(uint32_t*)&l01), "r"(*(uint32_t*)&l23) : "memory");
                }
            }
        }
        __syncthreads();

        // ---- mainloop: warp computes rows wm*16..+15, cols wn*64..+63 --------
        float acc[8][4];
#pragma unroll
        for (int nb = 0; nb < 8; nb++)
#pragma unroll
            for (int j = 0; j < 4; j++) acc[nb][j] = 0.f;

#pragma unroll
        for (int ks = 0; ks < 8; ks++) {
            uint32_t ahr[4], alr[4];
            {
                int c2a = ks * 2 + akh;
                int swa = (c2a & 8) | ((c2a ^ ar) & 7);
                uint32_t aoff = (uint32_t)(ar * 256 + (swa << 4));
                ldsm_x4(ahr[0], ahr[1], ahr[2], ahr[3], sb + SM_AHI + aoff);
                ldsm_x4(alr[0], alr[1], alr[2], alr[3], sb + SM_ALO + aoff);
            }
            uint32_t bf[8][4];
#pragma unroll
            for (int nb = 0; nb < 8; nb++) {
                int brow = (wn * 8 + nb) * 8 + bn;
                int c2 = ks * 2 + bkh;
                int sw = (c2 & 8) | ((c2 ^ brow) & 7);
                ldsm_x4(bf[nb][0], bf[nb][1], bf[nb][2], bf[nb][3],
                        bRegion + brow * 256 + (sw << 4));
            }
#pragma unroll
            for (int nb = 0; nb < 8; nb++)
                mma16816(acc[nb], ahr[0], ahr[1], ahr[2], ahr[3], bf[nb][0], bf[nb][1]);
#pragma unroll
            for (int nb = 0; nb < 8; nb++)
                mma16816(acc[nb], ahr[0], ahr[1], ahr[2], ahr[3], bf[nb][2], bf[nb][3]);
#pragma unroll
            for (int nb = 0; nb < 8; nb++)
                mma16816(acc[nb], alr[0], alr[1], alr[2], alr[3], bf[nb][0], bf[nb][1]);
        }

        // ---- epilogue --------------------------------------------------------
        int r0 = rowBase + wm * 16 + (lane >> 2);
        int r1 = r0 + 8;
        float nd0 = 1.f, nd1 = 1.f;
        if (EPI == 1) {
            if (r0 < NN) nd0 = g_ndst[r0];
            if (r1 < NN) nd1 = g_ndst[r1];
        }
        float ns0 = 1.f, ns1 = 1.f;
        if (OUT == 1) {
            if (r0 < NN) ns0 = g_nsrc[r0];
            if (r1 < NN) ns1 = g_nsrc[r1];
        }
#pragma unroll
        for (int nb = 0; nb < 8; nb++) {
            int col = wn * 64 + nb * 8 + (lane & 3) * 2;
            float bx = sbias[col], by = sbias[col + 1];
            float2 v0, v1;
            if (EPI == 1) {
                v0.x = fmaf(acc[nb][0], nd0, bx); v0.y = fmaf(acc[nb][1], nd0, by);
                v1.x = fmaf(acc[nb][2], nd1, bx); v1.y = fmaf(acc[nb][3], nd1, by);
            } else {
                v0.x = acc[nb][0] + bx; v0.y = acc[nb][1] + by;
                v1.x = acc[nb][2] + bx; v1.y = acc[nb][3] + by;
            }
            if (OUT == 0) {
                if (r0 < NN) ((float2*)Cext)[(size_t)r0 * 64 + (col >> 1)] = v0;
                if (r1 < NN) ((float2*)Cext)[(size_t)r1 * 64 + (col >> 1)] = v1;
            } else if (OUT == 1) {
                __half2 m0 = __floats2half2_rn(fmaxf(v0.x, 0.f) * ns0, fmaxf(v0.y, 0.f) * ns0);
                __half2 m1 = __floats2half2_rn(fmaxf(v1.x, 0.f) * ns1, fmaxf(v1.y, 0.f) * ns1);
                if (r0 < NN) ((__half2*)msgWr)[(size_t)r0 * 64 + (col >> 1)] = m0;
                if (r1 < NN) ((__half2*)msgWr)[(size_t)r1 * 64 + (col >> 1)] = m1;
            } else {
                __nv_bfloat162 h0 = __floats2bfloat162_rn(v0.x, v0.y);
                __nv_bfloat162 l0 = __floats2bfloat162_rn(
                    v0.x - __bfloat162float(__low2bfloat16(h0)),
                    v0.y - __bfloat162float(__high2bfloat16(h0)));
                __nv_bfloat162 h1 = __floats2bfloat162_rn(v1.x, v1.y);
                __nv_bfloat162 l1 = __floats2bfloat162_rn(
                    v1.x - __bfloat162float(__low2bfloat16(h1)),
                    v1.y - __bfloat162float(__high2bfloat16(h1)));
                if (r0 < NN) {
                    ((uint32_t*)g_Ahi)[(size_t)r0 * 64 + (col >> 1)] = *(uint32_t*)&h0;
                    ((uint32_t*)g_Alo)[(size_t)r0 * 64 + (col >> 1)] = *(uint32_t*)&l0;
                }
                if (r1 < NN) {
                    ((uint32_t*)g_Ahi)[(size_t)r1 * 64 + (col >> 1)] = *(uint32_t*)&h1;
                    ((uint32_t*)g_Alo)[(size_t)r1 * 64 + (col >> 1)] = *(uint32_t*)&l1;
                }
            }
            if (STATS) {
                float s0 = 0.f, s1 = 0.f, q0 = 0.f, q1 = 0.f;
                if (r0 < NN) { s0 += v0.x; s1 += v0.y; q0 += v0.x * v0.x; q1 += v0.y * v0.y; }
                if (r1 < NN) { s0 += v1.x; s1 += v1.y; q0 += v1.x * v1.x; q1 += v1.y * v1.y; }
#pragma unroll
                for (int off = 16; off >= 4; off >>= 1) {
                    s0 += __shfl_down_sync(0xffffffff, s0, off);
                    s1 += __shfl_down_sync(0xffffffff, s1, off);
                    q0 += __shfl_down_sync(0xffffffff, q0, off);
                    q1 += __shfl_down_sync(0xffffffff, q1, off);
                }
                if (lane < 4) {
                    sst[nb][0] += s0; sst[nb][1] += s1;
                    sst[nb][2] += q0; sst[nb][3] += q1;
                }
            }
        }
    }

    // ---- stats finalize (once per CTA) --------------------------------------
    if (STATS) {
        float* ssum = (float*)(smem + SM_STATS);          // [4][128]
        float* ssq  = (float*)(smem + SM_STATS + 2048);   // [4][128]
        __syncthreads();
        if (lane < 4) {
#pragma unroll
            for (int nb = 0; nb < 8; nb++) {
                int c0 = wn * 64 + nb * 8 + lane * 2;
                ssum[wm * DD + c0] = sst[nb][0]; ssum[wm * DD + c0 + 1] = sst[nb][1];
                ssq[wm * DD + c0] = sst[nb][2];  ssq[wm * DD + c0 + 1] = sst[nb][3];
            }
        }
        __syncthreads();
        if (tid < DD) {
            float ss = 0.f, qq = 0.f;
#pragma unroll
            for (int w = 0; w < 4; w++) {
                ss += ssum[w * DD + tid];
                qq += ssq[w * DD + tid];
            }
            atomicAdd(&g_colsum[tid], ss);
            atomicAdd(&g_colsq[tid], qq);
        }
    }
}

// ======================= launch =============================================
extern "C" void kernel_launch(void* const* d_in, const int* in_sizes, int n_in,
                              void* d_out, int out_size)
{
    const float* in_feat = (const float*)d_in[0];
    const int*   src     = (const int*)d_in[1];
    const int*   dst     = (const int*)d_in[2];
    const float* W1      = (const float*)d_in[3];
    const float* b1      = (const float*)d_in[4];
    const float* gamma   = (const float*)d_in[5];
    const float* beta    = (const float*)d_in[6];
    const float* W2      = (const float*)d_in[7];
    const float* b2      = (const float*)d_in[8];
    const float* Wc      = (const float*)d_in[9];
    const float* bc      = (const float*)d_in[10];
    float* out = (float*)d_out;

    cudaFuncSetAttribute(gemm_mma<0,0,2,1,0>, cudaFuncAttributeMaxDynamicSharedMemorySize, SM_TOTAL);
    cudaFuncSetAttribute(gemm_mma<1,0,1,0,1>, cudaFuncAttributeMaxDynamicSharedMemorySize, SM_TOTAL);
    cudaFuncSetAttribute(gemm_mma<3,1,1,0,0>, cudaFuncAttributeMaxDynamicSharedMemorySize, SM_TOTAL);
    cudaFuncSetAttribute(gemm_mma<3,1,1,0,1>, cudaFuncAttributeMaxDynamicSharedMemorySize, SM_TOTAL);
    cudaFuncSetAttribute(gemm_mma<3,1,0,0,0>, cudaFuncAttributeMaxDynamicSharedMemorySize, SM_TOTAL);

    const int nbN    = (NN + 255) / 256;
    const int nbE    = (NE + 255) / 256;
    const int nbScan = (NN + 1023) / 1024;      // 98

    // ---- fork: graph-structure chain on side stream -------------------------
    cudaStream_t s2;
    cudaEvent_t evFork, evJoin;
    cudaStreamCreateWithFlags(&s2, cudaStreamNonBlocking);
    cudaEventCreateWithFlags(&evFork, cudaEventDisableTiming);
    cudaEventCreateWithFlags(&evJoin, cudaEventDisableTiming);

    cudaEventRecord(evFork, 0);
    cudaStreamWaitEvent(s2, evFork, 0);

    init_graph_k<<<nbN, 256, 0, s2>>>();
    degree_k<<<nbE, 256, 0, s2>>>(src, dst);
    scanA_k<<<nbScan, 1024, 0, s2>>>();
    scanB_k<<<1, 128, 0, s2>>>(nbScan);
    scanC_k<<<nbN, 256, 0, s2>>>();
    csrfill_k<<<nbE, 256, 0, s2>>>(src, dst);
    cudaEventRecord(evJoin, s2);

    // ---- main stream ---------------------------------------------------------
    prep_w_all<<<192, 256>>>(W1, W2, Wc);
    gemm_mma<0,0,2,1,0><<<GRID_P, 256, SM_TOTAL>>>(in_feat, 0, b1, nullptr);  // -> split h0 (+stats)
    bn_finalize_k<<<1, 128>>>(gamma, beta);
    cudaStreamWaitEvent(0, evJoin, 0);
    // GEMM2: MSGSEL=1 -> writes msgA
    gemm_mma<1,0,1,0,1><<<GRID_P, 256, SM_TOTAL>>>(nullptr, 1, b2, nullptr);

    // ---- fused gather+GEMM propagation x3 (ping-pong msg buffers) -----------
    gemm_mma<3,1,1,0,0><<<GRID_P, 256, SM_TOTAL>>>(nullptr, 2, bc, nullptr);  // read A -> write B
    gemm_mma<3,1,1,0,1><<<GRID_P, 256, SM_TOTAL>>>(nullptr, 2, bc, nullptr);  // read B -> write A
    gemm_mma<3,1,0,0,0><<<GRID_P, 256, SM_TOTAL>>>(nullptr, 2, bc, out);      // read A -> d_out

    cudaEventDestroy(evFork);
    cudaEventDestroy(evJoin);
    cudaStreamDestroy(s2);
}

// round 16
// speedup vs baseline: 2.6022x; 2.6022x over previous
#include <cuda_runtime.h>
#include <cuda_bf16.h>
#include <cuda_fp16.h>
#include <cstdint>

#define NN 100000
#define NE 1600000
#define DD 128
#define NB_TILES 1563          // ceil(NN/64)
#define GRID_P 296             // 2 CTAs/SM x 148 SMs

// ======================= helpers ============================================
__device__ __forceinline__ uint32_t smem_to_u32(const void* p) {
    uint32_t a;
    asm("{ .reg .u64 t; cvta.to.shared.u64 t, %1; cvt.u32.u64 %0, t; }" : "=r"(a) : "l"(p));
    return a;
}
__device__ __forceinline__ void ldsm_x4(uint32_t& r0, uint32_t& r1, uint32_t& r2, uint32_t& r3,
                                        uint32_t addr) {
    asm volatile("ldmatrix.sync.aligned.m8n8.x4.shared.b16 {%0,%1,%2,%3}, [%4];"
                 : "=r"(r0), "=r"(r1), "=r"(r2), "=r"(r3) : "r"(addr));
}
__device__ __forceinline__ void mma16816(float* c, uint32_t a0, uint32_t a1, uint32_t a2,
                                         uint32_t a3, uint32_t b0, uint32_t b1) {
    asm volatile("mma.sync.aligned.m16n8k16.row.col.f32.bf16.bf16.f32 "
                 "{%0,%1,%2,%3}, {%4,%5,%6,%7}, {%8,%9}, {%0,%1,%2,%3};"
                 : "+f"(c[0]), "+f"(c[1]), "+f"(c[2]), "+f"(c[3])
                 : "r"(a0), "r"(a1), "r"(a2), "r"(a3), "r"(b0), "r"(b1));
}
// swizzled byte offset of bf16 element (r, c) in a row=256B tile
__device__ __host__ __forceinline__ uint32_t sw_off(int r, int c) {
    int c2 = c >> 3;
    int sw = (c2 & 8) | ((c2 ^ r) & 7);
    return (uint32_t)(r * 256 + (sw << 4) + (c & 7) * 2);
}
// swizzled offset of a whole 16B chunk
__device__ __forceinline__ uint32_t sw_chunk(int r, int chunk) {
    int sw = (chunk & 8) | ((chunk ^ r) & 7);
    return (uint32_t)(r * 256 + (sw << 4));
}

// ======================= scratch (device globals) ===========================
__device__ __align__(16) __nv_bfloat16 g_Ahi[(size_t)NN * DD];  // h0 / agg hi image
__device__ __align__(16) __nv_bfloat16 g_Alo[(size_t)NN * DD];  // h0 / agg lo image
__device__ __align__(16) __half g_msg[(size_t)NN * DD];         // relu(h)*nsrc, fp16
__device__ float  g_colsum[DD];
__device__ float  g_colsq[DD];
__device__ float  g_bnscale[DD];
__device__ float  g_bnshift[DD];
__device__ int    g_outdeg[NN];
__device__ int    g_indeg[NN];
__device__ float  g_nsrc[NN];
__device__ float  g_ndst[NN];
__device__ int    g_rowptr[NN + 1];
__device__ int    g_cursor[NN];
__device__ int    g_csrsrc[NE];
__device__ int    g_bsums[128];
__device__ __align__(16) __nv_bfloat16 g_Whi[3][16384];
__device__ __align__(16) __nv_bfloat16 g_Wlo[3][16384];

// ======================= graph-side kernels =================================
__global__ void init_graph_k() {
    int i = blockIdx.x * blockDim.x + threadIdx.x;
    if (i < NN) { g_outdeg[i] = 0; g_indeg[i] = 0; }
}

__global__ void degree_k(const int* __restrict__ src, const int* __restrict__ dst) {
    int i = blockIdx.x * blockDim.x + threadIdx.x;
    if (i < NE) {
        atomicAdd(&g_outdeg[src[i]], 1);
        atomicAdd(&g_indeg[dst[i]], 1);
    }
}

__global__ void scanA_k() {
    __shared__ int sdata[1024];
    int t = threadIdx.x;
    int i = blockIdx.x * 1024 + t;
    int x = (i < NN) ? g_indeg[i] : 0;
    if (i < NN) {
        g_nsrc[i] = rsqrtf((float)max(g_outdeg[i], 1));
        g_ndst[i] = rsqrtf((float)max(x, 1));
    }
    sdata[t] = x;
    __syncthreads();
    for (int off = 1; off < 1024; off <<= 1) {
        int v = (t >= off) ? sdata[t - off] : 0;
        __syncthreads();
        sdata[t] += v;
        __syncthreads();
    }
    if (i < NN) g_rowptr[i] = sdata[t] - x;
    if (t == 1023) g_bsums[blockIdx.x] = sdata[1023];
}

__global__ void scanB_k(int nblocks) {
    __shared__ int s[128];
    int t = threadIdx.x;
    int v = (t < nblocks) ? g_bsums[t] : 0;
    s[t] = v;
    __syncthreads();
    for (int off = 1; off < 128; off <<= 1) {
        int u = (t >= off) ? s[t - off] : 0;
        __syncthreads();
        s[t] += u;
        __syncthreads();
    }
    if (t < nblocks) g_bsums[t] = s[t] - v;
}

__global__ void scanC_k() {
    int i = blockIdx.x * blockDim.x + threadIdx.x;
    if (i < NN) {
        int v = g_rowptr[i] + g_bsums[i >> 10];
        g_rowptr[i] = v;
        g_cursor[i] = v;
    }
    if (i == 0) g_rowptr[NN] = NE;
}

__global__ void csrfill_k(const int* __restrict__ src, const int* __restrict__ dst) {
    int i = blockIdx.x * blockDim.x + threadIdx.x;
    if (i < NE) {
        int pos = atomicAdd(&g_cursor[dst[i]], 1);
        g_csrsrc[pos] = src[i];
    }
}

// ======================= MLP-side small kernels =============================
__global__ void prep_w_all(const float* __restrict__ W1, const float* __restrict__ W2,
                           const float* __restrict__ Wc) {
    if (blockIdx.x == 0 && threadIdx.x < DD) {
        g_colsum[threadIdx.x] = 0.f;
        g_colsq[threadIdx.x] = 0.f;
    }
    int slot = blockIdx.x >> 6;
    const float* W = (slot == 0) ? W1 : (slot == 1) ? W2 : Wc;
    int idx = (blockIdx.x & 63) * 256 + threadIdx.x;
    int n = idx >> 7, k = idx & 127;
    float w = W[k * DD + n];
    __nv_bfloat16 hi = __float2bfloat16(w);
    float r = w - __bfloat162float(hi);
    __nv_bfloat16 lo = __float2bfloat16(r);
    uint32_t o = sw_off(n, k) >> 1;
    g_Whi[slot][o] = hi;
    g_Wlo[slot][o] = lo;
}

__global__ void bn_finalize_k(const float* __restrict__ gamma, const float* __restrict__ beta) {
    int c = threadIdx.x;
    if (c < DD) {
        float inv_n = 1.f / (float)NN;
        float mean = g_colsum[c] * inv_n;
        float var = g_colsq[c] * inv_n - mean * mean;
        float rs = rsqrtf(var + 1e-5f);
        float gsc = gamma[c] * rs;
        g_bnscale[c] = gsc;
        g_bnshift[c] = beta[c] - mean * gsc;
    }
}

// ======================= persistent tensor-core GEMM ========================
// Grid-stride over 64-row tiles; B images loaded ONCE per CTA.
// ALOAD: 0 cvt from fp32 ext, 1 bn+relu from split h0 images, 2 copy split images.
// EPI:   0 v=acc+bias, 1 v=acc*ndst+bias.
// OUT:   0 fp32 -> Cext, 1 fp16 msg = relu(v)*nsrc, 2 split bf16 images.
// STATS: accumulate column sum/sumsq of v (register-resident across tiles).
#define SM_BIAS  0
#define SM_AHI   1024
#define SM_ALO   17408
#define SM_BHI   33792
#define SM_BLO   66560
#define SM_STATS 99328
#define SM_TOTAL 103424

template <int ALOAD, int EPI, int OUT, int STATS>
__global__ void __launch_bounds__(256, 2)
gemm_mma(const float* __restrict__ Aext,
         int wslot,
         const float* __restrict__ bias,
         float* __restrict__ Cext)
{
    extern __shared__ char smem[];
    uint32_t sb = smem_to_u32(smem);
    int tid = threadIdx.x;
    int lane = tid & 31;
    int wid = tid >> 5;
    int wm = wid >> 1;          // 0..3 : M split (16 rows each)
    int wn = wid & 1;           // 0..1 : N split (64 cols each)

    if (tid < 32) ((float4*)(smem + SM_BIAS))[tid] = ((const float4*)bias)[tid];

    // B images: load ONCE (2 x 32 KB, pre-swizzled layout)
    {
        const uint4* bh = (const uint4*)g_Whi[wslot];
        const uint4* bl = (const uint4*)g_Wlo[wslot];
        uint4* sh = (uint4*)(smem + SM_BHI);
        uint4* sl = (uint4*)(smem + SM_BLO);
#pragma unroll
        for (int i = 0; i < 8; i++) {
            sh[tid + i * 256] = bh[tid + i * 256];
            sl[tid + i * 256] = bl[tid + i * 256];
        }
    }

    // register-resident stats accumulators (valid on lanes 0-3)
    float sst[STATS ? 8 : 1][4];
    if (STATS)
#pragma unroll
        for (int nb = 0; nb < 8; nb++)
#pragma unroll
            for (int j = 0; j < 4; j++) sst[nb][j] = 0.f;

    const int ar = wm * 16 + (lane & 15);
    const int akh = lane >> 4;
    const int bn = lane & 7;
    const int bkh = (lane >> 3) & 1;
    const uint32_t bRegion = sb + ((lane >> 4) ? SM_BLO : SM_BHI);
    const float* sbias = (const float*)(smem + SM_BIAS);

    for (int tile = blockIdx.x; tile < NB_TILES; tile += GRID_P) {
        int rowBase = tile * 64;
        __syncthreads();   // prev mainloop done with smem A (and B copy on iter 0)

        // ---- A tile fill (64 rows) ------------------------------------------
        if (ALOAD == 0) {
            // fp32 external -> split bf16, swizzled
#pragma unroll
            for (int i = 0; i < 8; i++) {
                int t = tid + i * 256;          // 0..2047
                int r = t >> 5, q = t & 31;
                int gr = rowBase + r;
                float4 v = make_float4(0.f, 0.f, 0.f, 0.f);
                if (gr < NN) v = ((const float4*)Aext)[(size_t)gr * 32 + q];
                __nv_bfloat162 h01 = __floats2bfloat162_rn(v.x, v.y);
                __nv_bfloat162 h23 = __floats2bfloat162_rn(v.z, v.w);
                float lx = v.x - __bfloat162float(__low2bfloat16(h01));
                float ly = v.y - __bfloat162float(__high2bfloat16(h01));
                float lz = v.z - __bfloat162float(__low2bfloat16(h23));
                float lw = v.w - __bfloat162float(__high2bfloat16(h23));
                __nv_bfloat162 l01 = __floats2bfloat162_rn(lx, ly);
                __nv_bfloat162 l23 = __floats2bfloat162_rn(lz, lw);
                uint32_t off = sw_off(r, q * 4);
                asm volatile("st.shared.v2.b32 [%0], {%1, %2};" :: "r"(sb + SM_AHI + off),
                             "r"(*(uint32_t*)&h01), "r"(*(uint32_t*)&h23) : "memory");
                asm volatile("st.shared.v2.b32 [%0], {%1, %2};" :: "r"(sb + SM_ALO + off),
                             "r"(*(uint32_t*)&l01), "r"(*(uint32_t*)&l23) : "memory");
            }
        } else if (ALOAD == 1) {
            // split h0 images -> reconstruct, BN+ReLU, re-split
#pragma unroll
            for (int i = 0; i < 8; i++) {
                int t = tid + i * 256;          // 0..2047
                int r = t >> 5, q = t & 31;     // row, uint32 col-pair (2 cols)
                int gr = rowBase + r;
                uint32_t hw = 0, lw2 = 0, hw2 = 0, lw3 = 0;
                if (gr < NN) {
                    hw = ((const uint32_t*)g_Ahi)[(size_t)gr * 64 + q * 2 + 0];
                    lw2 = ((const uint32_t*)g_Ahi)[(size_t)gr * 64 + q * 2 + 1];
                    hw2 = ((const uint32_t*)g_Alo)[(size_t)gr * 64 + q * 2 + 0];
                    lw3 = ((const uint32_t*)g_Alo)[(size_t)gr * 64 + q * 2 + 1];
                }
                float4 sc = ((const float4*)g_bnscale)[q];
                float4 shp = ((const float4*)g_bnshift)[q];
                __nv_bfloat162 ha = *(__nv_bfloat162*)&hw;
                __nv_bfloat162 la = *(__nv_bfloat162*)&hw2;
                __nv_bfloat162 hb = *(__nv_bfloat162*)&lw2;
                __nv_bfloat162 lb = *(__nv_bfloat162*)&lw3;
                float f0 = __bfloat162float(__low2bfloat16(ha)) + __bfloat162float(__low2bfloat16(la));
                float f1 = __bfloat162float(__high2bfloat16(ha)) + __bfloat162float(__high2bfloat16(la));
                float f2 = __bfloat162float(__low2bfloat16(hb)) + __bfloat162float(__low2bfloat16(lb));
                float f3 = __bfloat162float(__high2bfloat16(hb)) + __bfloat162float(__high2bfloat16(lb));
                f0 = fmaxf(fmaf(f0, sc.x, shp.x), 0.f);
                f1 = fmaxf(fmaf(f1, sc.y, shp.y), 0.f);
                f2 = fmaxf(fmaf(f2, sc.z, shp.z), 0.f);
                f3 = fmaxf(fmaf(f3, sc.w, shp.w), 0.f);
                __nv_bfloat162 h01 = __floats2bfloat162_rn(f0, f1);
                __nv_bfloat162 h23 = __floats2bfloat162_rn(f2, f3);
                __nv_bfloat162 l01 = __floats2bfloat162_rn(
                    f0 - __bfloat162float(__low2bfloat16(h01)),
                    f1 - __bfloat162float(__high2bfloat16(h01)));
                __nv_bfloat162 l23 = __floats2bfloat162_rn(
                    f2 - __bfloat162float(__low2bfloat16(h23)),
                    f3 - __bfloat162float(__high2bfloat16(h23)));
                uint32_t off = sw_off(r, q * 4);
                asm volatile("st.shared.v2.b32 [%0], {%1, %2};" :: "r"(sb + SM_AHI + off),
                             "r"(*(uint32_t*)&h01), "r"(*(uint32_t*)&h23) : "memory");
                asm volatile("st.shared.v2.b32 [%0], {%1, %2};" :: "r"(sb + SM_ALO + off),
                             "r"(*(uint32_t*)&l01), "r"(*(uint32_t*)&l23) : "memory");
            }
        } else {
            // ALOAD==2: straight copy of split bf16 images (64 rows x 16 chunks)
#pragma unroll
            for (int i = 0; i < 4; i++) {
                int t = tid + i * 256;          // 0..1023
                int r = t >> 4, chunk = t & 15;
                int gr = rowBase + r;
                uint4 hv = make_uint4(0, 0, 0, 0), lv = make_uint4(0, 0, 0, 0);
                if (gr < NN) {
                    hv = ((const uint4*)g_Ahi)[(size_t)gr * 16 + chunk];
                    lv = ((const uint4*)g_Alo)[(size_t)gr * 16 + chunk];
                }
                uint32_t off = sw_chunk(r, chunk);
                *(uint4*)(smem + SM_AHI + off) = hv;
                *(uint4*)(smem + SM_ALO + off) = lv;
            }
        }
        __syncthreads();

        // ---- mainloop: warp computes rows wm*16..+15, cols wn*64..+63 --------
        float acc[8][4];
#pragma unroll
        for (int nb = 0; nb < 8; nb++)
#pragma unroll
            for (int j = 0; j < 4; j++) acc[nb][j] = 0.f;

#pragma unroll
        for (int ks = 0; ks < 8; ks++) {
            uint32_t ahr[4], alr[4];
            {
                int c2a = ks * 2 + akh;
                int swa = (c2a & 8) | ((c2a ^ ar) & 7);
                uint32_t aoff = (uint32_t)(ar * 256 + (swa << 4));
                ldsm_x4(ahr[0], ahr[1], ahr[2], ahr[3], sb + SM_AHI + aoff);
                ldsm_x4(alr[0], alr[1], alr[2], alr[3], sb + SM_ALO + aoff);
            }
            uint32_t bf[8][4];
#pragma unroll
            for (int nb = 0; nb < 8; nb++) {
                int brow = (wn * 8 + nb) * 8 + bn;
                int c2 = ks * 2 + bkh;
                int sw = (c2 & 8) | ((c2 ^ brow) & 7);
                ldsm_x4(bf[nb][0], bf[nb][1], bf[nb][2], bf[nb][3],
                        bRegion + brow * 256 + (sw << 4));
            }
#pragma unroll
            for (int nb = 0; nb < 8; nb++)
                mma16816(acc[nb], ahr[0], ahr[1], ahr[2], ahr[3], bf[nb][0], bf[nb][1]);
#pragma unroll
            for (int nb = 0; nb < 8; nb++)
                mma16816(acc[nb], ahr[0], ahr[1], ahr[2], ahr[3], bf[nb][2], bf[nb][3]);
#pragma unroll
            for (int nb = 0; nb < 8; nb++)
                mma16816(acc[nb], alr[0], alr[1], alr[2], alr[3], bf[nb][0], bf[nb][1]);
        }

        // ---- epilogue --------------------------------------------------------
        int r0 = rowBase + wm * 16 + (lane >> 2);
        int r1 = r0 + 8;
        float nd0 = 1.f, nd1 = 1.f;
        if (EPI == 1) {
            if (r0 < NN) nd0 = g_ndst[r0];
            if (r1 < NN) nd1 = g_ndst[r1];
        }
        float ns0 = 1.f, ns1 = 1.f;
        if (OUT == 1) {
            if (r0 < NN) ns0 = g_nsrc[r0];
            if (r1 < NN) ns1 = g_nsrc[r1];
        }
#pragma unroll
        for (int nb = 0; nb < 8; nb++) {
            int col = wn * 64 + nb * 8 + (lane & 3) * 2;
            float bx = sbias[col], by = sbias[col + 1];
            float2 v0, v1;
            if (EPI == 1) {
                v0.x = fmaf(acc[nb][0], nd0, bx); v0.y = fmaf(acc[nb][1], nd0, by);
                v1.x = fmaf(acc[nb][2], nd1, bx); v1.y = fmaf(acc[nb][3], nd1, by);
            } else {
                v0.x = acc[nb][0] + bx; v0.y = acc[nb][1] + by;
                v1.x = acc[nb][2] + bx; v1.y = acc[nb][3] + by;
            }
            if (OUT == 0) {
                if (r0 < NN) ((float2*)Cext)[(size_t)r0 * 64 + (col >> 1)] = v0;
                if (r1 < NN) ((float2*)Cext)[(size_t)r1 * 64 + (col >> 1)] = v1;
            } else if (OUT == 1) {
                __half2 m0 = __floats2half2_rn(fmaxf(v0.x, 0.f) * ns0, fmaxf(v0.y, 0.f) * ns0);
                __half2 m1 = __floats2half2_rn(fmaxf(v1.x, 0.f) * ns1, fmaxf(v1.y, 0.f) * ns1);
                if (r0 < NN) ((__half2*)g_msg)[(size_t)r0 * 64 + (col >> 1)] = m0;
                if (r1 < NN) ((__half2*)g_msg)[(size_t)r1 * 64 + (col >> 1)] = m1;
            } else {
                __nv_bfloat162 h0 = __floats2bfloat162_rn(v0.x, v0.y);
                __nv_bfloat162 l0 = __floats2bfloat162_rn(
                    v0.x - __bfloat162float(__low2bfloat16(h0)),
                    v0.y - __bfloat162float(__high2bfloat16(h0)));
                __nv_bfloat162 h1 = __floats2bfloat162_rn(v1.x, v1.y);
                __nv_bfloat162 l1 = __floats2bfloat162_rn(
                    v1.x - __bfloat162float(__low2bfloat16(h1)),
                    v1.y - __bfloat162float(__high2bfloat16(h1)));
                if (r0 < NN) {
                    ((uint32_t*)g_Ahi)[(size_t)r0 * 64 + (col >> 1)] = *(uint32_t*)&h0;
                    ((uint32_t*)g_Alo)[(size_t)r0 * 64 + (col >> 1)] = *(uint32_t*)&l0;
                }
                if (r1 < NN) {
                    ((uint32_t*)g_Ahi)[(size_t)r1 * 64 + (col >> 1)] = *(uint32_t*)&h1;
                    ((uint32_t*)g_Alo)[(size_t)r1 * 64 + (col >> 1)] = *(uint32_t*)&l1;
                }
            }
            if (STATS) {
                float s0 = 0.f, s1 = 0.f, q0 = 0.f, q1 = 0.f;
                if (r0 < NN) { s0 += v0.x; s1 += v0.y; q0 += v0.x * v0.x; q1 += v0.y * v0.y; }
                if (r1 < NN) { s0 += v1.x; s1 += v1.y; q0 += v1.x * v1.x; q1 += v1.y * v1.y; }
#pragma unroll
                for (int off = 16; off >= 4; off >>= 1) {
                    s0 += __shfl_down_sync(0xffffffff, s0, off);
                    s1 += __shfl_down_sync(0xffffffff, s1, off);
                    q0 += __shfl_down_sync(0xffffffff, q0, off);
                    q1 += __shfl_down_sync(0xffffffff, q1, off);
                }
                if (lane < 4) {
                    sst[nb][0] += s0; sst[nb][1] += s1;
                    sst[nb][2] += q0; sst[nb][3] += q1;
                }
            }
        }
    }

    // ---- stats finalize (once per CTA) --------------------------------------
    if (STATS) {
        float* ssum = (float*)(smem + SM_STATS);          // [4][128]
        float* ssq  = (float*)(smem + SM_STATS + 2048);   // [4][128]
        __syncthreads();
        if (lane < 4) {
#pragma unroll
            for (int nb = 0; nb < 8; nb++) {
                int c0 = wn * 64 + nb * 8 + lane * 2;
                ssum[wm * DD + c0] = sst[nb][0]; ssum[wm * DD + c0 + 1] = sst[nb][1];
                ssq[wm * DD + c0] = sst[nb][2];  ssq[wm * DD + c0 + 1] = sst[nb][3];
            }
        }
        __syncthreads();
        if (tid < DD) {
            float ss = 0.f, qq = 0.f;
#pragma unroll
            for (int w = 0; w < 4; w++) {
                ss += ssum[w * DD + tid];
                qq += ssq[w * DD + tid];
            }
            atomicAdd(&g_colsum[tid], ss);
            atomicAdd(&g_colsq[tid], qq);
        }
    }
}

// ======================= pull-side edge gather (fp16 msg -> split bf16) =====
__global__ void gather_k() {
    int node = blockIdx.x * 8 + (threadIdx.x >> 5);
    if (node >= NN) return;
    int lane = threadIdx.x & 31;
    int e = g_rowptr[node];
    int end = g_rowptr[node + 1];
    float4 acc = make_float4(0.f, 0.f, 0.f, 0.f);
    const uint2* m = (const uint2*)g_msg;
    if (e < end) {
        int s = g_csrsrc[e];
        while (true) {
            e++;
            int sn = (e < end) ? g_csrsrc[e] : 0;
            uint2 v = m[(size_t)s * 32 + lane];
            float2 f0 = __half22float2(*(const __half2*)&v.x);
            float2 f1 = __half22float2(*(const __half2*)&v.y);
            acc.x += f0.x; acc.y += f0.y; acc.z += f1.x; acc.w += f1.y;
            if (e >= end) break;
            s = sn;
        }
    }
    // write split bf16 (cols lane*4..+3)
    __nv_bfloat162 h01 = __floats2bfloat162_rn(acc.x, acc.y);
    __nv_bfloat162 h23 = __floats2bfloat162_rn(acc.z, acc.w);
    __nv_bfloat162 l01 = __floats2bfloat162_rn(
        acc.x - __bfloat162float(__low2bfloat16(h01)),
        acc.y - __bfloat162float(__high2bfloat16(h01)));
    __nv_bfloat162 l23 = __floats2bfloat162_rn(
        acc.z - __bfloat162float(__low2bfloat16(h23)),
        acc.w - __bfloat162float(__high2bfloat16(h23)));
    uint2 hv, lv;
    hv.x = *(uint32_t*)&h01; hv.y = *(uint32_t*)&h23;
    lv.x = *(uint32_t*)&l01; lv.y = *(uint32_t*)&l23;
    ((uint2*)g_Ahi)[(size_t)node * 32 + lane] = hv;
    ((uint2*)g_Alo)[(size_t)node * 32 + lane] = lv;
}

// ======================= launch =============================================
extern "C" void kernel_launch(void* const* d_in, const int* in_sizes, int n_in,
                              void* d_out, int out_size)
{
    const float* in_feat = (const float*)d_in[0];
    const int*   src     = (const int*)d_in[1];
    const int*   dst     = (const int*)d_in[2];
    const float* W1      = (const float*)d_in[3];
    const float* b1      = (const float*)d_in[4];
    const float* gamma   = (const float*)d_in[5];
    const float* beta    = (const float*)d_in[6];
    const float* W2      = (const float*)d_in[7];
    const float* b2      = (const float*)d_in[8];
    const float* Wc      = (const float*)d_in[9];
    const float* bc      = (const float*)d_in[10];
    float* out = (float*)d_out;

    cudaFuncSetAttribute(gemm_mma<0,0,2,1>, cudaFuncAttributeMaxDynamicSharedMemorySize, SM_TOTAL);
    cudaFuncSetAttribute(gemm_mma<1,0,1,0>, cudaFuncAttributeMaxDynamicSharedMemorySize, SM_TOTAL);
    cudaFuncSetAttribute(gemm_mma<2,1,1,0>, cudaFuncAttributeMaxDynamicSharedMemorySize, SM_TOTAL);
    cudaFuncSetAttribute(gemm_mma<2,1,0,0>, cudaFuncAttributeMaxDynamicSharedMemorySize, SM_TOTAL);

    const int nbN    = (NN + 255) / 256;
    const int nbE    = (NE + 255) / 256;
    const int nbScan = (NN + 1023) / 1024;      // 98

    // ---- fork: graph-structure chain on side stream -------------------------
    cudaStream_t s2;
    cudaEvent_t evFork, evJoin;
    cudaStreamCreateWithFlags(&s2, cudaStreamNonBlocking);
    cudaEventCreateWithFlags(&evFork, cudaEventDisableTiming);
    cudaEventCreateWithFlags(&evJoin, cudaEventDisableTiming);

    cudaEventRecord(evFork, 0);
    cudaStreamWaitEvent(s2, evFork, 0);

    init_graph_k<<<nbN, 256, 0, s2>>>();
    degree_k<<<nbE, 256, 0, s2>>>(src, dst);
    scanA_k<<<nbScan, 1024, 0, s2>>>();
    scanB_k<<<1, 128, 0, s2>>>(nbScan);
    scanC_k<<<nbN, 256, 0, s2>>>();
    csrfill_k<<<nbE, 256, 0, s2>>>(src, dst);
    cudaEventRecord(evJoin, s2);

    // ---- main stream ---------------------------------------------------------
    prep_w_all<<<192, 256>>>(W1, W2, Wc);
    gemm_mma<0,0,2,1><<<GRID_P, 256, SM_TOTAL>>>(in_feat, 0, b1, nullptr);  // -> split h0 (+stats)
    bn_finalize_k<<<1, 128>>>(gamma, beta);
    cudaStreamWaitEvent(0, evJoin, 0);
    gemm_mma<1,0,1,0><<<GRID_P, 256, SM_TOTAL>>>(nullptr, 1, b2, nullptr);  // -> g_msg

    // ---- propagation x3: standalone gather + persistent GEMM -----------------
    for (int step = 0; step < 3; step++) {
        gather_k<<<NN / 8, 256>>>();                                         // msg -> split agg
        if (step < 2)
            gemm_mma<2,1,1,0><<<GRID_P, 256, SM_TOTAL>>>(nullptr, 2, bc, nullptr); // -> g_msg
        else
            gemm_mma<2,1,0,0><<<GRID_P, 256, SM_TOTAL>>>(nullptr, 2, bc, out);     // -> d_out
    }

    cudaEventDestroy(evFork);
    cudaEventDestroy(evJoin);
    cudaStreamDestroy(s2);
}